// round 1
// baseline (speedup 1.0000x reference)
#include <cuda_runtime.h>
#include <cstdint>

// Problem constants
#define NGRAPH 512
#define NPG    125          // nodes per graph
#define D      128          // hidden
#define SH     69           // S_HID
#define SHP    80           // padded S_HID
#define NC     10           // clusters
#define HS_LD  129          // padded row stride for H in smem

// d_out float offsets (outputs concatenated in return order)
#define P1_OFF  0
#define P2_OFF  1024
#define IND_OFF 2048
#define S_OFF   2560
#define E_OFF   642560
#define Q_OFF   1297920

// ---------------------------------------------------------------------------
// Kernel 1: per-graph fused  S = softmax(relu(H w1 + b1) w2 + b2),
//           E = S^T H.  One block per graph, 256 threads.
// ---------------------------------------------------------------------------
__global__ __launch_bounds__(256) void ciflow_k1(
    const float* __restrict__ H,   // [64000,128]
    const float* __restrict__ w1,  // [128,69]
    const float* __restrict__ b1,  // [69]
    const float* __restrict__ w2,  // [69,10]
    const float* __restrict__ b2,  // [10]
    float* __restrict__ out)
{
    extern __shared__ float sm[];
    float* Hs  = sm;                    // [128][129]  (rows 125..127 zero)
    float* W1s = Hs + 128 * HS_LD;      // [128][80]   (aliased by As later)
    float* W2s = W1s + 128 * SHP;       // [80][10]
    float* Ss  = W2s + SHP * NC;        // [128][10]
    float* b1s = Ss + 128 * NC;         // [80]
    float* b2s = b1s + SHP;             // [16]

    const int g   = blockIdx.x;
    const int tid = threadIdx.x;

    // ---- cooperative loads --------------------------------------------------
    const float* Hg = H + (size_t)g * NPG * D;
    for (int idx = tid; idx < NPG * D; idx += 256) {
        int m = idx >> 7, k = idx & 127;
        Hs[m * HS_LD + k] = Hg[idx];
    }
    for (int idx = tid; idx < 3 * HS_LD; idx += 256)   // zero pad rows 125..127
        Hs[NPG * HS_LD + idx] = 0.0f;
    for (int idx = tid; idx < 128 * SHP; idx += 256) {
        int k = idx / SHP, n = idx - k * SHP;
        W1s[idx] = (n < SH) ? w1[k * SH + n] : 0.0f;
    }
    for (int idx = tid; idx < SHP * NC; idx += 256) {
        int n = idx / NC, c = idx - n * NC;
        W2s[idx] = (n < SH) ? w2[n * NC + c] : 0.0f;
    }
    if (tid < SHP) b1s[tid] = (tid < SH) ? b1[tid] : 0.0f;
    if (tid < NC)  b2s[tid] = b2[tid];
    __syncthreads();

    // ---- stage A: A[m][n] = relu(sum_k H[m][k] w1[k][n] + b1[n]) ------------
    // 16x16 thread grid, tile 8 rows x 5 cols, interleaved (stride 16).
    const int tx = tid & 15;   // M
    const int ty = tid >> 4;   // N
    float acc[8][5];
#pragma unroll
    for (int i = 0; i < 8; ++i)
#pragma unroll
        for (int j = 0; j < 5; ++j) acc[i][j] = 0.0f;

#pragma unroll 2
    for (int k = 0; k < 128; ++k) {
        float h[8], w[5];
#pragma unroll
        for (int i = 0; i < 8; ++i) h[i] = Hs[(tx + 16 * i) * HS_LD + k];
#pragma unroll
        for (int j = 0; j < 5; ++j) w[j] = W1s[k * SHP + ty + 16 * j];
#pragma unroll
        for (int i = 0; i < 8; ++i)
#pragma unroll
            for (int j = 0; j < 5; ++j) acc[i][j] = fmaf(h[i], w[j], acc[i][j]);
    }
    __syncthreads();           // all W1s reads done before aliasing
    float* As = W1s;           // reuse smem
#pragma unroll
    for (int i = 0; i < 8; ++i)
#pragma unroll
        for (int j = 0; j < 5; ++j) {
            int n = ty + 16 * j;
            As[(tx + 16 * i) * SHP + n] = fmaxf(acc[i][j] + b1s[n], 0.0f);
        }
    __syncthreads();

    // ---- stage Z: z = A w2 + b2, softmax -> S -------------------------------
    if (tid < NPG) {
        const int m = tid;
        float z[NC];
#pragma unroll
        for (int c = 0; c < NC; ++c) z[c] = b2s[c];
        for (int n = 0; n < SHP; ++n) {
            float a = As[m * SHP + n];
#pragma unroll
            for (int c = 0; c < NC; ++c) z[c] = fmaf(a, W2s[n * NC + c], z[c]);
        }
        float mx = z[0];
#pragma unroll
        for (int c = 1; c < NC; ++c) mx = fmaxf(mx, z[c]);
        float ssum = 0.0f;
#pragma unroll
        for (int c = 0; c < NC; ++c) { z[c] = expf(z[c] - mx); ssum += z[c]; }
        float inv = 1.0f / ssum;
        float* srow = &Ss[m * NC];
        float* gout = out + S_OFF + ((size_t)g * NPG + m) * NC;
#pragma unroll
        for (int c = 0; c < NC; ++c) {
            float s = z[c] * inv;
            srow[c] = s;
            gout[c] = s;
        }
    }
    __syncthreads();

    // ---- stage E: E[c][d] = sum_m S[m][c] H[m][d] ---------------------------
    const int d  = tid & 127;
    const int c0 = (tid >> 7) * 5;
    float e[5] = {0.f, 0.f, 0.f, 0.f, 0.f};
    for (int m = 0; m < NPG; ++m) {
        float h = Hs[m * HS_LD + d];
#pragma unroll
        for (int j = 0; j < 5; ++j) e[j] = fmaf(Ss[m * NC + c0 + j], h, e[j]);
    }
    float* Eout = out + E_OFF + (size_t)g * (NC * D);
#pragma unroll
    for (int j = 0; j < 5; ++j) Eout[(c0 + j) * D + d] = e[j];
}

// ---------------------------------------------------------------------------
// Threefry-2x32 (JAX-compatible)
// ---------------------------------------------------------------------------
__device__ __forceinline__ void threefry2x32(uint32_t k0, uint32_t k1,
                                             uint32_t c0, uint32_t c1,
                                             uint32_t& y0, uint32_t& y1)
{
    uint32_t ks2 = k0 ^ k1 ^ 0x1BD11BDAu;
    uint32_t x0 = c0 + k0, x1 = c1 + k1;
#define TF_RND(r) { x0 += x1; x1 = (x1 << (r)) | (x1 >> (32 - (r))); x1 ^= x0; }
    TF_RND(13) TF_RND(15) TF_RND(26) TF_RND(6)  x0 += k1;  x1 += ks2 + 1u;
    TF_RND(17) TF_RND(29) TF_RND(16) TF_RND(24) x0 += ks2; x1 += k0  + 2u;
    TF_RND(13) TF_RND(15) TF_RND(26) TF_RND(6)  x0 += k0;  x1 += k1  + 3u;
    TF_RND(17) TF_RND(29) TF_RND(16) TF_RND(24) x0 += k1;  x1 += ks2 + 4u;
    TF_RND(13) TF_RND(15) TF_RND(26) TF_RND(6)  x0 += ks2; x1 += k0  + 5u;
#undef TF_RND
    y0 = x0; y1 = x1;
}

// jax_threefry_partitionable=True path: bits[f] = y0 ^ y1 for counter (0, f)
__device__ __forceinline__ uint32_t jax_bits_partitionable(uint32_t f)
{
    uint32_t y0, y1;
    threefry2x32(0u, 42u, 0u, f, y0, y1);
    return y0 ^ y1;
}

__device__ __forceinline__ float jax_unit_uniform(uint32_t bits)
{
    float f = __uint_as_float((bits >> 9) | 0x3f800000u) - 1.0f;
    return (f == 0.0f) ? 1.17549435e-38f : f;   // minval = finfo(f32).tiny
}

// ---------------------------------------------------------------------------
// Kernel 2: everything downstream of E_all. One block per graph, 128 threads.
// ---------------------------------------------------------------------------
__global__ __launch_bounds__(128) void ciflow_k2(
    const int*   __restrict__ targets,
    const float* __restrict__ wf,    // [1280,2]
    const float* __restrict__ bf,    // [2]
    const float* __restrict__ p1,    // [128,8]
    const float* __restrict__ pb1,   // [8]
    const float* __restrict__ p2,    // [8,16]
    const float* __restrict__ pb2,   // [16]
    const float* __restrict__ ci,    // corr_inter [2,16]
    const float* __restrict__ cia,   // corr_intra [2,16]
    float* __restrict__ out)
{
    __shared__ float Es[1280];
    __shared__ float wfs[2560];
    __shared__ float p1s[1024];
    __shared__ float p2s[128];
    __shared__ float pb1s[8], pb2s[16];
    __shared__ float corrs[32], cmask[16];
    __shared__ float ts[80], qraw[160], fms[10];
    __shared__ float red[8];
    __shared__ float sc[2];

    const int g   = blockIdx.x;
    const int tid = threadIdx.x;
    const int lane = tid & 31, wid = tid >> 5;

    const float* Eg = out + E_OFF + (size_t)g * 1280;
    for (int i = tid; i < 1280; i += 128) Es[i]  = Eg[i];
    for (int i = tid; i < 2560; i += 128) wfs[i] = wf[i];
    for (int i = tid; i < 1024; i += 128) p1s[i] = p1[i];
    if (tid < 128) p2s[tid] = p2[tid];
    if (tid < 8)   pb1s[tid] = pb1[tid];
    if (tid < 16)  pb2s[tid] = pb2[tid];
    __syncthreads();

    // ---- pred1 --------------------------------------------------------------
    float s0 = 0.f, s1 = 0.f;
    for (int i = tid; i < 1280; i += 128) {
        float e = Es[i];
        s0 = fmaf(e, wfs[2 * i], s0);
        s1 = fmaf(e, wfs[2 * i + 1], s1);
    }
#pragma unroll
    for (int off = 16; off; off >>= 1) {
        s0 += __shfl_down_sync(0xffffffffu, s0, off);
        s1 += __shfl_down_sync(0xffffffffu, s1, off);
    }
    if (lane == 0) { red[wid * 2] = s0; red[wid * 2 + 1] = s1; }
    __syncthreads();

    if (tid == 0) {
        float z0 = red[0] + red[2] + red[4] + red[6] + bf[0];
        float z1 = red[1] + red[3] + red[5] + red[7] + bf[1];
        out[P1_OFF + g * 2 + 0] = z0;
        out[P1_OFF + g * 2 + 1] = z1;
        float mx = fmaxf(z0, z1);
        float e0 = expf(z0 - mx), e1 = expf(z1 - mx);
        float inv = 1.0f / (e0 + e1);
        float pp0 = e0 * inv, pp1 = e1 * inv;

        // categorical sample (key 42, logits log(p+1e-12))
        float u0 = jax_unit_uniform(jax_bits_partitionable(2u * g));
        float u1 = jax_unit_uniform(jax_bits_partitionable(2u * g + 1u));
        float g0 = -logf(-logf(u0));
        float g1 = -logf(-logf(u1));
        float l0 = logf(pp0 + 1e-12f) + g0;
        float l1 = logf(pp1 + 1e-12f) + g1;
        int sample = (l1 > l0) ? 1 : 0;       // argmax, ties -> index 0

        out[IND_OFF + g] = (sample == targets[g]) ? 1.0f : 0.0f;
        sc[0] = pp0 + ((sample == 0) ? (1.0f - pp0) : -pp0);
        sc[1] = pp1 + ((sample == 1) ? (1.0f - pp1) : -pp1);
    }

    // ---- correlation = softmax(ci, axis=0) * softmax(cia, axis=1) -----------
    if (tid < 32) {
        int c = tid >> 4, f = tid & 15;
        float a0 = ci[f], a1 = ci[16 + f];
        float m = fmaxf(a0, a1);
        float e0 = expf(a0 - m), e1 = expf(a1 - m);
        float colv = ((c == 0) ? e0 : e1) / (e0 + e1);
        float rm = -1e30f;
        for (int ff = 0; ff < 16; ++ff) rm = fmaxf(rm, cia[c * 16 + ff]);
        float rs = 0.f;
        for (int ff = 0; ff < 16; ++ff) rs += expf(cia[c * 16 + ff] - rm);
        corrs[c * 16 + f] = colv * (expf(cia[c * 16 + f] - rm) / rs);
    }
    __syncthreads();

    if (tid < 16) cmask[tid] = sc[0] * corrs[tid] + sc[1] * corrs[16 + tid];
    __syncthreads();

    // ---- Q = softmax(relu(E p1 + pb1) p2 + pb2) ------------------------------
    if (tid < 80) {
        int c = tid >> 3, j = tid & 7;
        float a = pb1s[j];
        for (int k = 0; k < 128; ++k) a = fmaf(Es[c * 128 + k], p1s[k * 8 + j], a);
        ts[tid] = fmaxf(a, 0.0f);
    }
    __syncthreads();
    for (int idx = tid; idx < 160; idx += 128) {
        int c = idx >> 4, f = idx & 15;
        float a = pb2s[f];
#pragma unroll
        for (int j = 0; j < 8; ++j) a = fmaf(ts[c * 8 + j], p2s[j * 16 + f], a);
        qraw[idx] = a;
    }
    __syncthreads();
    if (tid < 10) {
        int c = tid;
        float mx = -1e30f;
        for (int f = 0; f < 16; ++f) mx = fmaxf(mx, qraw[c * 16 + f]);
        float ssum = 0.f;
        for (int f = 0; f < 16; ++f) ssum += expf(qraw[c * 16 + f] - mx);
        float inv = 1.0f / ssum;
        float fm = 0.f;
        float* qout = out + Q_OFF + (size_t)g * 160 + c * 16;
        for (int f = 0; f < 16; ++f) {
            float q = expf(qraw[c * 16 + f] - mx) * inv;
            qout[f] = q;
            fm = fmaf(q, cmask[f], fm);
        }
        fms[c] = fm;
    }
    __syncthreads();

    // ---- pred2 = (fm[c] * E).reshape @ wf + bf -------------------------------
    s0 = 0.f; s1 = 0.f;
    for (int i = tid; i < 1280; i += 128) {
        float e = fms[i >> 7] * Es[i];
        s0 = fmaf(e, wfs[2 * i], s0);
        s1 = fmaf(e, wfs[2 * i + 1], s1);
    }
#pragma unroll
    for (int off = 16; off; off >>= 1) {
        s0 += __shfl_down_sync(0xffffffffu, s0, off);
        s1 += __shfl_down_sync(0xffffffffu, s1, off);
    }
    if (lane == 0) { red[wid * 2] = s0; red[wid * 2 + 1] = s1; }
    __syncthreads();
    if (tid == 0) {
        out[P2_OFF + g * 2 + 0] = red[0] + red[2] + red[4] + red[6] + bf[0];
        out[P2_OFF + g * 2 + 1] = red[1] + red[3] + red[5] + red[7] + bf[1];
    }
}

// ---------------------------------------------------------------------------
extern "C" void kernel_launch(void* const* d_in, const int* in_sizes, int n_in,
                              void* d_out, int out_size)
{
    const float* H   = (const float*)d_in[0];
    // d_in[1] = batch (implicitly 125 nodes/graph, sorted) - unused
    const int*   tgt = (const int*)  d_in[2];
    const float* w1  = (const float*)d_in[3];
    const float* b1  = (const float*)d_in[4];
    const float* w2  = (const float*)d_in[5];
    const float* b2  = (const float*)d_in[6];
    const float* wf  = (const float*)d_in[7];
    const float* bf  = (const float*)d_in[8];
    const float* p1  = (const float*)d_in[9];
    const float* pb1 = (const float*)d_in[10];
    const float* p2  = (const float*)d_in[11];
    const float* pb2 = (const float*)d_in[12];
    const float* ci  = (const float*)d_in[13];
    const float* cia = (const float*)d_in[14];
    float* out = (float*)d_out;

    const int smem1 = (128 * HS_LD + 128 * SHP + SHP * NC + 128 * NC + SHP + 16) * 4;
    static bool attr_set = false;
    if (!attr_set) {
        cudaFuncSetAttribute(ciflow_k1, cudaFuncAttributeMaxDynamicSharedMemorySize, smem1);
        attr_set = true;
    }

    ciflow_k1<<<NGRAPH, 256, smem1>>>(H, w1, b1, w2, b2, out);
    ciflow_k2<<<NGRAPH, 128>>>(tgt, wf, bf, p1, pb1, p2, pb2, ci, cia, out);
}